// round 3
// baseline (speedup 1.0000x reference)
#include <cuda_runtime.h>
#include <stdint.h>

#define N_NODES 16384
#define CIN     128
#define HC      256     // HEADS * OUT_CH
#define OUTC    128
#define E_EDGES 196608
#define DHW     8192
#define BATCH   2
#define NEG_ATT 0.2f
#define NEG_ACT 0.01f

// ---- scratch (device globals; no allocation allowed) ----
__device__ __align__(16) float  g_h[N_NODES * HC];        // 16 MB, L2-resident
__device__ __align__(16) float  g_pre[N_NODES * OUTC];    // 8 MB pre-BN output
__device__ int    g_cnt[N_NODES];
__device__ int    g_rowstart[N_NODES];
__device__ int    g_fill[N_NODES];
__device__ int    g_csr[E_EDGES];
__device__ double g_sum[OUTC];
__device__ double g_sq[OUTC];
__device__ float  g_scale[OUTC];
__device__ float  g_shift[OUTC];

// ---------------- K0: zero counters / BN accumulators ----------------
__global__ void k_zero() {
    int i = blockIdx.x * blockDim.x + threadIdx.x;
    if (i < N_NODES) g_cnt[i] = 0;
    if (i < OUTC) { g_sum[i] = 0.0; g_sq[i] = 0.0; }
}

// ---------------- K1: h = xf @ W + b  (16 nodes per block) ----------------
// xf[n][k] = x[b][k][s], n = b*DHW + s. Block handles nodes n0..n0+15,
// 256 threads each own one output column for all 16 nodes.
__global__ void k_gemm(const float* __restrict__ x,
                       const float* __restrict__ w,
                       const float* __restrict__ bias) {
    __shared__ float sh[16 * CIN];   // layout sh[k*16 + m]
    int tid = threadIdx.x;
    int n0  = blockIdx.x * 16;
    int b   = n0 / DHW;
    int s0  = n0 % DHW;

    #pragma unroll 4
    for (int idx = tid; idx < 16 * CIN; idx += 256) {
        int m = idx & 15, k = idx >> 4;
        sh[idx] = x[(size_t)b * CIN * DHW + (size_t)k * DHW + (s0 + m)];
    }
    __syncthreads();

    float acc[16];
    #pragma unroll
    for (int m = 0; m < 16; m++) acc[m] = 0.f;

    const float4* shv = (const float4*)sh;
    #pragma unroll 2
    for (int k = 0; k < CIN; k++) {
        float wk = __ldg(&w[k * HC + tid]);
        float4 a0 = shv[k * 4 + 0];
        float4 a1 = shv[k * 4 + 1];
        float4 a2 = shv[k * 4 + 2];
        float4 a3 = shv[k * 4 + 3];
        acc[0]  += a0.x * wk;  acc[1]  += a0.y * wk;
        acc[2]  += a0.z * wk;  acc[3]  += a0.w * wk;
        acc[4]  += a1.x * wk;  acc[5]  += a1.y * wk;
        acc[6]  += a1.z * wk;  acc[7]  += a1.w * wk;
        acc[8]  += a2.x * wk;  acc[9]  += a2.y * wk;
        acc[10] += a2.z * wk;  acc[11] += a2.w * wk;
        acc[12] += a3.x * wk;  acc[13] += a3.y * wk;
        acc[14] += a3.z * wk;  acc[15] += a3.w * wk;
    }
    float bb = __ldg(&bias[tid]);
    #pragma unroll
    for (int m = 0; m < 16; m++)
        g_h[(size_t)(n0 + m) * HC + tid] = acc[m] + bb;
}

// ---------------- K2: in-degree count (edge_index is int32) ----------------
__global__ void k_deg(const int* __restrict__ ei) {
    int e = blockIdx.x * blockDim.x + threadIdx.x;
    if (e < E_EDGES) {
        unsigned d = (unsigned)ei[E_EDGES + e];
        if (d < N_NODES) atomicAdd(&g_cnt[d], 1);
    }
}

// ---------------- K3: exclusive scan of degrees (1 block, 1024 thr) -------
__global__ void k_scan() {
    __shared__ int sh[1024];
    int t = threadIdx.x;
    int base = t * 16;
    int loc[16];
    int run = 0;
    #pragma unroll
    for (int i = 0; i < 16; i++) { loc[i] = run; run += g_cnt[base + i]; }
    sh[t] = run;
    __syncthreads();
    for (int off = 1; off < 1024; off <<= 1) {
        int v = (t >= off) ? sh[t - off] : 0;
        __syncthreads();
        sh[t] += v;
        __syncthreads();
    }
    int excl = sh[t] - run;
    #pragma unroll
    for (int i = 0; i < 16; i++) {
        int rs = excl + loc[i];
        g_rowstart[base + i] = rs;
        g_fill[base + i]     = rs;
    }
}

// ---------------- K4: scatter edges into CSR-by-dst ----------------
__global__ void k_scatter(const int* __restrict__ ei) {
    int e = blockIdx.x * blockDim.x + threadIdx.x;
    if (e < E_EDGES) {
        unsigned d = (unsigned)ei[E_EDGES + e];
        unsigned s = (unsigned)ei[e];
        if (d < N_NODES && s < N_NODES) {
            int pos = atomicAdd(&g_fill[d], 1);
            g_csr[pos] = (int)s;
        }
    }
}

// ---------------- K5: per-node GATv2 with online softmax ----------------
// 1 warp per node. Lane l owns flat channels 8l..8l+7 of the 256-wide h row
// (lanes 0..15 = head0, 16..31 = head1).
#define LR(v) fmaxf((v), NEG_ATT * (v))

__device__ __forceinline__ float edge_score(
    float4 h0, float4 h1, float4 d0, float4 d1, float4 a0, float4 a1) {
    float s;
    s  = LR(h0.x + d0.x) * a0.x;
    s += LR(h0.y + d0.y) * a0.y;
    s += LR(h0.z + d0.z) * a0.z;
    s += LR(h0.w + d0.w) * a0.w;
    s += LR(h1.x + d1.x) * a1.x;
    s += LR(h1.y + d1.y) * a1.y;
    s += LR(h1.z + d1.z) * a1.z;
    s += LR(h1.w + d1.w) * a1.w;
    // reduce within the 16-lane half (head)
    s += __shfl_xor_sync(0xffffffffu, s, 8);
    s += __shfl_xor_sync(0xffffffffu, s, 4);
    s += __shfl_xor_sync(0xffffffffu, s, 2);
    s += __shfl_xor_sync(0xffffffffu, s, 1);
    return s;
}

__global__ void k_attn(const float* __restrict__ att,
                       const float* __restrict__ gat_bias) {
    int warp = (blockIdx.x * blockDim.x + threadIdx.x) >> 5;
    int lane = threadIdx.x & 31;
    if (warp >= N_NODES) return;
    int i = warp;

    const float4* hp = (const float4*)g_h;           // 64 float4 per node row
    float4 hd0 = __ldg(&hp[(size_t)i * 64 + lane * 2]);
    float4 hd1 = __ldg(&hp[(size_t)i * 64 + lane * 2 + 1]);
    const float4* ap = (const float4*)att;
    float4 at0 = __ldg(&ap[lane * 2]);
    float4 at1 = __ldg(&ap[lane * 2 + 1]);

    // self loop (src = i): p = 1
    float m = edge_score(hd0, hd1, hd0, hd1, at0, at1);
    float den = 1.0f;
    float acc[8] = { hd0.x, hd0.y, hd0.z, hd0.w, hd1.x, hd1.y, hd1.z, hd1.w };

    int start = g_rowstart[i];
    int deg   = g_cnt[i];
    for (int j = 0; j < deg; j++) {
        int src = g_csr[start + j];
        float4 s0 = __ldg(&hp[(size_t)src * 64 + lane * 2]);
        float4 s1 = __ldg(&hp[(size_t)src * 64 + lane * 2 + 1]);
        float s = edge_score(s0, s1, hd0, hd1, at0, at1);
        float p;
        if (s > m) {
            float sc = __expf(m - s);
            den *= sc;
            #pragma unroll
            for (int k = 0; k < 8; k++) acc[k] *= sc;
            m = s;
            p = 1.0f;
        } else {
            p = __expf(s - m);
        }
        den += p;
        acc[0] += p * s0.x; acc[1] += p * s0.y;
        acc[2] += p * s0.z; acc[3] += p * s0.w;
        acc[4] += p * s1.x; acc[5] += p * s1.y;
        acc[6] += p * s1.z; acc[7] += p * s1.w;
    }

    float inv = 1.0f / den;
    float q[8];
    #pragma unroll
    for (int k = 0; k < 8; k++) q[k] = acc[k] * inv;

    // head mean: lane l (<16) pairs with lane l+16 (same output channels)
    float o[8];
    #pragma unroll
    for (int k = 0; k < 8; k++) o[k] = __shfl_xor_sync(0xffffffffu, q[k], 16);

    if (lane < 16) {
        int c0 = lane * 8;
        float4 r0, r1;
        r0.x = 0.5f * (q[0] + o[0]) + __ldg(&gat_bias[c0 + 0]);
        r0.y = 0.5f * (q[1] + o[1]) + __ldg(&gat_bias[c0 + 1]);
        r0.z = 0.5f * (q[2] + o[2]) + __ldg(&gat_bias[c0 + 2]);
        r0.w = 0.5f * (q[3] + o[3]) + __ldg(&gat_bias[c0 + 3]);
        r1.x = 0.5f * (q[4] + o[4]) + __ldg(&gat_bias[c0 + 4]);
        r1.y = 0.5f * (q[5] + o[5]) + __ldg(&gat_bias[c0 + 5]);
        r1.z = 0.5f * (q[6] + o[6]) + __ldg(&gat_bias[c0 + 6]);
        r1.w = 0.5f * (q[7] + o[7]) + __ldg(&gat_bias[c0 + 7]);
        float4* op = (float4*)g_pre;
        op[(size_t)i * 32 + lane * 2]     = r0;
        op[(size_t)i * 32 + lane * 2 + 1] = r1;
    }
}

// ---------------- K6: BN statistics (sum, sumsq per channel) -------------
__global__ void k_bnstats() {
    __shared__ float ssum[256], ssq[256];
    int c = threadIdx.x & 127;
    int g = threadIdx.x >> 7;          // 0 or 1
    int rbase = blockIdx.x * 128;
    float sum = 0.f, sq = 0.f;
    for (int r = rbase + g; r < rbase + 128; r += 2) {
        float v = g_pre[(size_t)r * 128 + c];
        sum += v; sq += v * v;
    }
    ssum[threadIdx.x] = sum;
    ssq[threadIdx.x]  = sq;
    __syncthreads();
    if (g == 0) {
        double S = (double)ssum[c] + (double)ssum[c + 128];
        double Q = (double)ssq[c]  + (double)ssq[c + 128];
        atomicAdd(&g_sum[c], S);
        atomicAdd(&g_sq[c], Q);
    }
}

// ---------------- K6b: fold BN into scale/shift ----------------
__global__ void k_bnfold(const float* __restrict__ gamma,
                         const float* __restrict__ beta) {
    int c = threadIdx.x;
    if (c < OUTC) {
        double mean = g_sum[c] / (double)N_NODES;
        double var  = g_sq[c] / (double)N_NODES - mean * mean;
        float inv = (float)(1.0 / sqrt(var + 1e-5));
        float a = gamma[c] * inv;
        g_scale[c] = a;
        g_shift[c] = beta[c] - (float)mean * a;
    }
}

// ---------------- K7: apply BN + LeakyReLU + layout transform ------------
__global__ void k_final(float* __restrict__ out) {
    int idx = blockIdx.x * blockDim.x + threadIdx.x;
    if (idx >= BATCH * OUTC * DHW) return;
    int s = idx % DHW;
    int c = (idx / DHW) % OUTC;
    int b = idx / (DHW * OUTC);
    int n = b * DHW + s;
    float v = g_pre[(size_t)n * 128 + c] * g_scale[c] + g_shift[c];
    out[idx] = fmaxf(v, NEG_ACT * v);
}

// ---------------- launch ----------------
extern "C" void kernel_launch(void* const* d_in, const int* in_sizes, int n_in,
                              void* d_out, int out_size) {
    const float* x        = (const float*)d_in[0];
    const int*   ei       = (const int*)d_in[1];     // int64 downcast to int32
    const float* lin_w    = (const float*)d_in[2];
    const float* lin_b    = (const float*)d_in[3];
    const float* att      = (const float*)d_in[4];
    const float* gat_bias = (const float*)d_in[5];
    const float* bn_gamma = (const float*)d_in[6];
    const float* bn_beta  = (const float*)d_in[7];
    float*       out      = (float*)d_out;

    k_zero<<<(N_NODES + 255) / 256, 256>>>();
    k_gemm<<<N_NODES / 16, 256>>>(x, lin_w, lin_b);
    k_deg<<<(E_EDGES + 255) / 256, 256>>>(ei);
    k_scan<<<1, 1024>>>();
    k_scatter<<<(E_EDGES + 255) / 256, 256>>>(ei);
    k_attn<<<(N_NODES * 32) / 128, 128>>>(att, gat_bias);
    k_bnstats<<<N_NODES / 128, 256>>>();
    k_bnfold<<<1, 128>>>(bn_gamma, bn_beta);
    k_final<<<(BATCH * OUTC * DHW + 255) / 256, 256>>>(out);
}

// round 6
// speedup vs baseline: 1.2581x; 1.2581x over previous
#include <cuda_runtime.h>
#include <stdint.h>

#define N_NODES 16384
#define CIN     128
#define HC      256     // HEADS * OUT_CH
#define OUTC    128
#define E_EDGES 196608
#define DHW     8192
#define BATCH   2
#define NEG_ATT 0.2f
#define NEG_ACT 0.01f

// ---- scratch (device globals; no allocation allowed) ----
__device__ __align__(16) float  g_h[N_NODES * HC];        // 16 MB, L2-resident
__device__ __align__(16) float  g_pre[N_NODES * OUTC];    // 8 MB pre-BN output
__device__ int    g_cnt[N_NODES];
__device__ int    g_rowstart[N_NODES];
__device__ int    g_fill[N_NODES];
__device__ int    g_partial[16];
__device__ int    g_csr[E_EDGES];
__device__ double g_sum[OUTC];
__device__ double g_sq[OUTC];
__device__ float  g_scale[OUTC];
__device__ float  g_shift[OUTC];

// ---------------- K0: zero counters / BN accumulators ----------------
__global__ void k_zero() {
    int i = blockIdx.x * blockDim.x + threadIdx.x;
    if (i < N_NODES) g_cnt[i] = 0;
    if (i < OUTC) { g_sum[i] = 0.0; g_sq[i] = 0.0; }
}

// ---------------- K1: h = xf @ W + b  (16 nodes per block) ----------------
__global__ void k_gemm(const float* __restrict__ x,
                       const float* __restrict__ w,
                       const float* __restrict__ bias) {
    __shared__ float sh[16 * CIN];   // layout sh[k*16 + m]
    int tid = threadIdx.x;
    int n0  = blockIdx.x * 16;
    int b   = n0 / DHW;
    int s0  = n0 % DHW;

    #pragma unroll 4
    for (int idx = tid; idx < 16 * CIN; idx += 256) {
        int m = idx & 15, k = idx >> 4;
        sh[idx] = x[(size_t)b * CIN * DHW + (size_t)k * DHW + (s0 + m)];
    }
    __syncthreads();

    float acc[16];
    #pragma unroll
    for (int m = 0; m < 16; m++) acc[m] = 0.f;

    const float4* shv = (const float4*)sh;
    #pragma unroll 2
    for (int k = 0; k < CIN; k++) {
        float wk = __ldg(&w[k * HC + tid]);
        float4 a0 = shv[k * 4 + 0];
        float4 a1 = shv[k * 4 + 1];
        float4 a2 = shv[k * 4 + 2];
        float4 a3 = shv[k * 4 + 3];
        acc[0]  += a0.x * wk;  acc[1]  += a0.y * wk;
        acc[2]  += a0.z * wk;  acc[3]  += a0.w * wk;
        acc[4]  += a1.x * wk;  acc[5]  += a1.y * wk;
        acc[6]  += a1.z * wk;  acc[7]  += a1.w * wk;
        acc[8]  += a2.x * wk;  acc[9]  += a2.y * wk;
        acc[10] += a2.z * wk;  acc[11] += a2.w * wk;
        acc[12] += a3.x * wk;  acc[13] += a3.y * wk;
        acc[14] += a3.z * wk;  acc[15] += a3.w * wk;
    }
    float bb = __ldg(&bias[tid]);
    #pragma unroll
    for (int m = 0; m < 16; m++)
        g_h[(size_t)(n0 + m) * HC + tid] = acc[m] + bb;
}

// ---------------- K2: in-degree count (edge_index is int32) ----------------
__global__ void k_deg(const int* __restrict__ ei) {
    int e = blockIdx.x * blockDim.x + threadIdx.x;
    if (e < E_EDGES) {
        unsigned d = (unsigned)ei[E_EDGES + e];
        if (d < N_NODES) atomicAdd(&g_cnt[d], 1);
    }
}

// ---------------- K3a: block-level inclusive scan (16 blocks x 1024) -------
__global__ void k_scanA() {
    __shared__ int sh[1024];
    int t = threadIdx.x;
    int g = blockIdx.x * 1024 + t;
    int v = g_cnt[g];
    sh[t] = v;
    __syncthreads();
    for (int off = 1; off < 1024; off <<= 1) {
        int u = (t >= off) ? sh[t - off] : 0;
        __syncthreads();
        sh[t] += u;
        __syncthreads();
    }
    g_rowstart[g] = sh[t] - v;            // exclusive within block
    if (t == 1023) g_partial[blockIdx.x] = sh[t];
}

// ---------------- K3b: add block offsets ----------------
__global__ void k_scanB() {
    __shared__ int off;
    int t = threadIdx.x, b = blockIdx.x;
    int g = b * 1024 + t;
    if (t == 0) {
        int o = 0;
        for (int i = 0; i < b; i++) o += g_partial[i];
        off = o;
    }
    __syncthreads();
    int rs = g_rowstart[g] + off;
    g_rowstart[g] = rs;
    g_fill[g]     = rs;
}

// ---------------- K4: scatter edges into CSR-by-dst ----------------
__global__ void k_scatter(const int* __restrict__ ei) {
    int e = blockIdx.x * blockDim.x + threadIdx.x;
    if (e < E_EDGES) {
        unsigned d = (unsigned)ei[E_EDGES + e];
        unsigned s = (unsigned)ei[e];
        if (d < N_NODES && s < N_NODES) {
            int pos = atomicAdd(&g_fill[d], 1);
            g_csr[pos] = (int)s;
        }
    }
}

// ---------------- K5: per-node GATv2, plain softmax (no max shift) --------
// 1 warp per node. Lane l owns flat channels 8l..8l+7 of the 256-wide h row
// (lanes 0..15 = head0, 16..31 = head1).
#define LR(v) fmaxf((v), NEG_ATT * (v))

__device__ __forceinline__ float edge_score(
    float4 h0, float4 h1, float4 d0, float4 d1, float4 a0, float4 a1) {
    float s;
    s  = LR(h0.x + d0.x) * a0.x;
    s += LR(h0.y + d0.y) * a0.y;
    s += LR(h0.z + d0.z) * a0.z;
    s += LR(h0.w + d0.w) * a0.w;
    s += LR(h1.x + d1.x) * a1.x;
    s += LR(h1.y + d1.y) * a1.y;
    s += LR(h1.z + d1.z) * a1.z;
    s += LR(h1.w + d1.w) * a1.w;
    s += __shfl_xor_sync(0xffffffffu, s, 8);
    s += __shfl_xor_sync(0xffffffffu, s, 4);
    s += __shfl_xor_sync(0xffffffffu, s, 2);
    s += __shfl_xor_sync(0xffffffffu, s, 1);
    return s;
}

__global__ void k_attn(const float* __restrict__ att,
                       const float* __restrict__ gat_bias) {
    int warp = (blockIdx.x * blockDim.x + threadIdx.x) >> 5;
    int lane = threadIdx.x & 31;
    if (warp >= N_NODES) return;
    int i = warp;

    const float4* hp = (const float4*)g_h;           // 64 float4 per node row
    float4 hd0 = __ldg(&hp[(size_t)i * 64 + lane * 2]);
    float4 hd1 = __ldg(&hp[(size_t)i * 64 + lane * 2 + 1]);
    const float4* ap = (const float4*)att;
    float4 at0 = __ldg(&ap[lane * 2]);
    float4 at1 = __ldg(&ap[lane * 2 + 1]);

    // self loop (src = i)
    float p0 = __expf(edge_score(hd0, hd1, hd0, hd1, at0, at1));
    float den = p0;
    float acc[8] = { p0 * hd0.x, p0 * hd0.y, p0 * hd0.z, p0 * hd0.w,
                     p0 * hd1.x, p0 * hd1.y, p0 * hd1.z, p0 * hd1.w };

    int start = g_rowstart[i];
    int deg   = g_cnt[i];
    int j = 0;
    for (; j + 2 <= deg; j += 2) {
        int srcA = __ldg(&g_csr[start + j]);
        int srcB = __ldg(&g_csr[start + j + 1]);
        float4 a0 = __ldg(&hp[(size_t)srcA * 64 + lane * 2]);
        float4 a1 = __ldg(&hp[(size_t)srcA * 64 + lane * 2 + 1]);
        float4 b0 = __ldg(&hp[(size_t)srcB * 64 + lane * 2]);
        float4 b1 = __ldg(&hp[(size_t)srcB * 64 + lane * 2 + 1]);
        float sA = edge_score(a0, a1, hd0, hd1, at0, at1);
        float sB = edge_score(b0, b1, hd0, hd1, at0, at1);
        float pA = __expf(sA);
        float pB = __expf(sB);
        den += pA + pB;
        acc[0] += pA * a0.x + pB * b0.x;
        acc[1] += pA * a0.y + pB * b0.y;
        acc[2] += pA * a0.z + pB * b0.z;
        acc[3] += pA * a0.w + pB * b0.w;
        acc[4] += pA * a1.x + pB * b1.x;
        acc[5] += pA * a1.y + pB * b1.y;
        acc[6] += pA * a1.z + pB * b1.z;
        acc[7] += pA * a1.w + pB * b1.w;
    }
    if (j < deg) {
        int src = __ldg(&g_csr[start + j]);
        float4 s0 = __ldg(&hp[(size_t)src * 64 + lane * 2]);
        float4 s1 = __ldg(&hp[(size_t)src * 64 + lane * 2 + 1]);
        float p = __expf(edge_score(s0, s1, hd0, hd1, at0, at1));
        den += p;
        acc[0] += p * s0.x; acc[1] += p * s0.y;
        acc[2] += p * s0.z; acc[3] += p * s0.w;
        acc[4] += p * s1.x; acc[5] += p * s1.y;
        acc[6] += p * s1.z; acc[7] += p * s1.w;
    }

    float inv = 1.0f / den;
    float q[8];
    #pragma unroll
    for (int k = 0; k < 8; k++) q[k] = acc[k] * inv;

    // head mean: lane l (<16) pairs with lane l+16 (same output channels)
    float o[8];
    #pragma unroll
    for (int k = 0; k < 8; k++) o[k] = __shfl_xor_sync(0xffffffffu, q[k], 16);

    if (lane < 16) {
        int c0 = lane * 8;
        float4 r0, r1;
        r0.x = 0.5f * (q[0] + o[0]) + __ldg(&gat_bias[c0 + 0]);
        r0.y = 0.5f * (q[1] + o[1]) + __ldg(&gat_bias[c0 + 1]);
        r0.z = 0.5f * (q[2] + o[2]) + __ldg(&gat_bias[c0 + 2]);
        r0.w = 0.5f * (q[3] + o[3]) + __ldg(&gat_bias[c0 + 3]);
        r1.x = 0.5f * (q[4] + o[4]) + __ldg(&gat_bias[c0 + 4]);
        r1.y = 0.5f * (q[5] + o[5]) + __ldg(&gat_bias[c0 + 5]);
        r1.z = 0.5f * (q[6] + o[6]) + __ldg(&gat_bias[c0 + 6]);
        r1.w = 0.5f * (q[7] + o[7]) + __ldg(&gat_bias[c0 + 7]);
        float4* op = (float4*)g_pre;
        op[(size_t)i * 32 + lane * 2]     = r0;
        op[(size_t)i * 32 + lane * 2 + 1] = r1;
    }
}

// ---------------- K6: BN statistics (sum, sumsq per channel) -------------
__global__ void k_bnstats() {
    __shared__ float ssum[256], ssq[256];
    int c = threadIdx.x & 127;
    int g = threadIdx.x >> 7;          // 0 or 1
    int rbase = blockIdx.x * 128;
    float sum = 0.f, sq = 0.f;
    for (int r = rbase + g; r < rbase + 128; r += 2) {
        float v = g_pre[(size_t)r * 128 + c];
        sum += v; sq += v * v;
    }
    ssum[threadIdx.x] = sum;
    ssq[threadIdx.x]  = sq;
    __syncthreads();
    if (g == 0) {
        double S = (double)ssum[c] + (double)ssum[c + 128];
        double Q = (double)ssq[c]  + (double)ssq[c + 128];
        atomicAdd(&g_sum[c], S);
        atomicAdd(&g_sq[c], Q);
    }
}

// ---------------- K6b: fold BN into scale/shift ----------------
__global__ void k_bnfold(const float* __restrict__ gamma,
                         const float* __restrict__ beta) {
    int c = threadIdx.x;
    if (c < OUTC) {
        double mean = g_sum[c] / (double)N_NODES;
        double var  = g_sq[c] / (double)N_NODES - mean * mean;
        float inv = (float)(1.0 / sqrt(var + 1e-5));
        float a = gamma[c] * inv;
        g_scale[c] = a;
        g_shift[c] = beta[c] - (float)mean * a;
    }
}

// ---------------- K7: BN + LeakyReLU + transpose (32x32 tiles) -----------
__global__ void k_final(float* __restrict__ out) {
    __shared__ float t[32][33];
    int c0 = blockIdx.y * 32;
    int s0 = blockIdx.x * 32;
    int b  = blockIdx.z;
    int x = threadIdx.x;          // 0..31
    int y = threadIdx.y;          // 0..7

    #pragma unroll
    for (int i = y; i < 32; i += 8)
        t[i][x] = g_pre[(size_t)(b * DHW + s0 + i) * 128 + c0 + x];
    __syncthreads();

    #pragma unroll
    for (int i = y; i < 32; i += 8) {
        int c = c0 + i;
        float v = t[x][i] * g_scale[c] + g_shift[c];
        out[((size_t)b * OUTC + c) * DHW + s0 + x] = fmaxf(v, NEG_ACT * v);
    }
}

// ---------------- launch ----------------
extern "C" void kernel_launch(void* const* d_in, const int* in_sizes, int n_in,
                              void* d_out, int out_size) {
    const float* x        = (const float*)d_in[0];
    const int*   ei       = (const int*)d_in[1];     // int64 downcast to int32
    const float* lin_w    = (const float*)d_in[2];
    const float* lin_b    = (const float*)d_in[3];
    const float* att      = (const float*)d_in[4];
    const float* gat_bias = (const float*)d_in[5];
    const float* bn_gamma = (const float*)d_in[6];
    const float* bn_beta  = (const float*)d_in[7];
    float*       out      = (float*)d_out;

    k_zero<<<(N_NODES + 255) / 256, 256>>>();
    k_gemm<<<N_NODES / 16, 256>>>(x, lin_w, lin_b);
    k_deg<<<(E_EDGES + 255) / 256, 256>>>(ei);
    k_scanA<<<16, 1024>>>();
    k_scanB<<<16, 1024>>>();
    k_scatter<<<(E_EDGES + 255) / 256, 256>>>(ei);
    k_attn<<<(N_NODES * 32) / 128, 128>>>(att, gat_bias);
    k_bnstats<<<N_NODES / 128, 256>>>();
    k_bnfold<<<1, 128>>>(bn_gamma, bn_beta);
    dim3 ftb(32, 8);
    dim3 fgr(DHW / 32, OUTC / 32, BATCH);
    k_final<<<fgr, ftb>>>(out);
}

// round 7
// speedup vs baseline: 1.2869x; 1.0228x over previous
#include <cuda_runtime.h>
#include <cuda_fp16.h>
#include <stdint.h>

#define N_NODES 16384
#define CIN     128
#define HC      256     // HEADS * OUT_CH
#define OUTC    128
#define E_EDGES 196608
#define DHW     8192
#define BATCH   2
#define NEG_ATT 0.2f
#define NEG_ACT 0.01f

// ---- scratch (device globals; no allocation allowed) ----
__device__ __align__(16) __half g_h2[N_NODES * HC];       // 8 MB, L2-resident
__device__ __align__(16) float  g_pre[N_NODES * OUTC];    // 8 MB pre-BN output
__device__ int    g_cnt[N_NODES];
__device__ int    g_rowstart[N_NODES];
__device__ int    g_fill[N_NODES];
__device__ volatile int g_partial[16];
__device__ volatile int g_flag[16];
__device__ int    g_csr[E_EDGES];
__device__ double g_sum[OUTC];
__device__ double g_sq[OUTC];

#define FMA2(d, a, b, c) \
    asm("fma.rn.f32x2 %0, %1, %2, %3;" : "=l"(d) : "l"(a), "l"(b), "l"(c))
#define UNPK(lo, hi, v) \
    asm("mov.b64 {%0,%1}, %2;" : "=f"(lo), "=f"(hi) : "l"(v))

// ---------------- K0: zero counters / BN accumulators / flags -------------
__global__ void k_zero() {
    int i = blockIdx.x * blockDim.x + threadIdx.x;
    if (i < N_NODES) g_cnt[i] = 0;
    if (i < OUTC) { g_sum[i] = 0.0; g_sq[i] = 0.0; }
    if (i < 16) g_flag[i] = 0;
}

// ---------------- K1: h = xf @ W + b with packed f32x2 FMA ----------------
// 16 nodes per block, 256 threads each own one output column. Node pairs are
// packed into 64-bit f32x2 registers (shared tile is node-major per k).
__global__ void k_gemm(const float* __restrict__ x,
                       const float* __restrict__ w,
                       const float* __restrict__ bias) {
    __shared__ __align__(16) float sh[16 * CIN];   // layout sh[k*16 + m]
    int tid = threadIdx.x;
    int n0  = blockIdx.x * 16;
    int b   = n0 / DHW;
    int s0  = n0 % DHW;

    #pragma unroll 4
    for (int idx = tid; idx < 16 * CIN; idx += 256) {
        int m = idx & 15, k = idx >> 4;
        sh[idx] = x[(size_t)b * CIN * DHW + (size_t)k * DHW + (s0 + m)];
    }
    __syncthreads();

    unsigned long long acc[8];
    #pragma unroll
    for (int p = 0; p < 8; p++) acc[p] = 0ull;

    #pragma unroll 2
    for (int k = 0; k < CIN; k++) {
        float wk = __ldg(&w[k * HC + tid]);
        unsigned wkb = __float_as_uint(wk);
        unsigned long long wk2;
        asm("mov.b64 %0, {%1,%1};" : "=l"(wk2) : "r"(wkb));
        const ulonglong2* shv = (const ulonglong2*)(sh + k * 16);
        ulonglong2 v0 = shv[0];
        ulonglong2 v1 = shv[1];
        ulonglong2 v2 = shv[2];
        ulonglong2 v3 = shv[3];
        FMA2(acc[0], v0.x, wk2, acc[0]);
        FMA2(acc[1], v0.y, wk2, acc[1]);
        FMA2(acc[2], v1.x, wk2, acc[2]);
        FMA2(acc[3], v1.y, wk2, acc[3]);
        FMA2(acc[4], v2.x, wk2, acc[4]);
        FMA2(acc[5], v2.y, wk2, acc[5]);
        FMA2(acc[6], v3.x, wk2, acc[6]);
        FMA2(acc[7], v3.y, wk2, acc[7]);
    }
    float bb = __ldg(&bias[tid]);
    #pragma unroll
    for (int p = 0; p < 8; p++) {
        float lo, hi;
        UNPK(lo, hi, acc[p]);
        g_h2[(size_t)(n0 + 2 * p)     * HC + tid] = __float2half_rn(lo + bb);
        g_h2[(size_t)(n0 + 2 * p + 1) * HC + tid] = __float2half_rn(hi + bb);
    }
}

// ---------------- K2: in-degree count (edge_index is int32) ----------------
__global__ void k_deg(const int* __restrict__ ei) {
    int e = blockIdx.x * blockDim.x + threadIdx.x;
    if (e < E_EDGES) {
        unsigned d = (unsigned)ei[E_EDGES + e];
        if (d < N_NODES) atomicAdd(&g_cnt[d], 1);
    }
}

// ---------------- K3: fused scan (16 blocks, flag-chained offsets) --------
__global__ void k_scan() {
    __shared__ int sh[1024];
    __shared__ int s_off;
    int t = threadIdx.x, b = blockIdx.x;
    int g = b * 1024 + t;
    int v = g_cnt[g];
    sh[t] = v;
    __syncthreads();
    for (int off = 1; off < 1024; off <<= 1) {
        int u = (t >= off) ? sh[t - off] : 0;
        __syncthreads();
        sh[t] += u;
        __syncthreads();
    }
    int incl = sh[t];
    if (t == 1023) {
        g_partial[b] = incl;
        __threadfence();
        g_flag[b] = 1;
    }
    if (t == 0) {
        int o = 0;
        for (int i = 0; i < b; i++) {
            while (g_flag[i] == 0) { }
            o += g_partial[i];
        }
        s_off = o;
    }
    __syncthreads();
    int rs = incl - v + s_off;
    g_rowstart[g] = rs;
    g_fill[g]     = rs;
}

// ---------------- K4: scatter edges into CSR-by-dst ----------------
__global__ void k_scatter(const int* __restrict__ ei) {
    int e = blockIdx.x * blockDim.x + threadIdx.x;
    if (e < E_EDGES) {
        unsigned d = (unsigned)ei[E_EDGES + e];
        unsigned s = (unsigned)ei[e];
        if (d < N_NODES && s < N_NODES) {
            int pos = atomicAdd(&g_fill[d], 1);
            g_csr[pos] = (int)s;
        }
    }
}

// ---------------- K5: per-node GATv2, fp16 h rows ----------------
// 1 warp per node. Lane l owns flat channels 8l..8l+7 (lanes 0..15 head0,
// 16..31 head1). One LDG.128 fetches a lane's 8 half-precision channels.
#define LR(v) fmaxf((v), NEG_ATT * (v))

__device__ __forceinline__ void ld_row(int node, int lane, float4& h0, float4& h1) {
    uint4 v = __ldg(((const uint4*)g_h2) + (size_t)node * 32 + lane);
    __half2* p = (__half2*)&v;
    float2 f0 = __half22float2(p[0]);
    float2 f1 = __half22float2(p[1]);
    float2 f2 = __half22float2(p[2]);
    float2 f3 = __half22float2(p[3]);
    h0 = make_float4(f0.x, f0.y, f1.x, f1.y);
    h1 = make_float4(f2.x, f2.y, f3.x, f3.y);
}

__device__ __forceinline__ float edge_score(
    float4 h0, float4 h1, float4 d0, float4 d1, float4 a0, float4 a1) {
    float s;
    s  = LR(h0.x + d0.x) * a0.x;
    s += LR(h0.y + d0.y) * a0.y;
    s += LR(h0.z + d0.z) * a0.z;
    s += LR(h0.w + d0.w) * a0.w;
    s += LR(h1.x + d1.x) * a1.x;
    s += LR(h1.y + d1.y) * a1.y;
    s += LR(h1.z + d1.z) * a1.z;
    s += LR(h1.w + d1.w) * a1.w;
    s += __shfl_xor_sync(0xffffffffu, s, 8);
    s += __shfl_xor_sync(0xffffffffu, s, 4);
    s += __shfl_xor_sync(0xffffffffu, s, 2);
    s += __shfl_xor_sync(0xffffffffu, s, 1);
    return s;
}

__global__ void k_attn(const float* __restrict__ att,
                       const float* __restrict__ gat_bias) {
    int warp = (blockIdx.x * blockDim.x + threadIdx.x) >> 5;
    int lane = threadIdx.x & 31;
    if (warp >= N_NODES) return;
    int i = warp;

    float4 hd0, hd1;
    ld_row(i, lane, hd0, hd1);
    const float4* ap = (const float4*)att;
    float4 at0 = __ldg(&ap[lane * 2]);
    float4 at1 = __ldg(&ap[lane * 2 + 1]);

    // self loop (src = i)
    float p0 = __expf(edge_score(hd0, hd1, hd0, hd1, at0, at1));
    float den = p0;
    float acc[8] = { p0 * hd0.x, p0 * hd0.y, p0 * hd0.z, p0 * hd0.w,
                     p0 * hd1.x, p0 * hd1.y, p0 * hd1.z, p0 * hd1.w };

    int start = g_rowstart[i];
    int deg   = g_cnt[i];
    int j = 0;
    for (; j + 2 <= deg; j += 2) {
        int srcA = __ldg(&g_csr[start + j]);
        int srcB = __ldg(&g_csr[start + j + 1]);
        float4 a0, a1, b0, b1;
        ld_row(srcA, lane, a0, a1);
        ld_row(srcB, lane, b0, b1);
        float sA = edge_score(a0, a1, hd0, hd1, at0, at1);
        float sB = edge_score(b0, b1, hd0, hd1, at0, at1);
        float pA = __expf(sA);
        float pB = __expf(sB);
        den += pA + pB;
        acc[0] += pA * a0.x + pB * b0.x;
        acc[1] += pA * a0.y + pB * b0.y;
        acc[2] += pA * a0.z + pB * b0.z;
        acc[3] += pA * a0.w + pB * b0.w;
        acc[4] += pA * a1.x + pB * b1.x;
        acc[5] += pA * a1.y + pB * b1.y;
        acc[6] += pA * a1.z + pB * b1.z;
        acc[7] += pA * a1.w + pB * b1.w;
    }
    if (j < deg) {
        int src = __ldg(&g_csr[start + j]);
        float4 s0, s1;
        ld_row(src, lane, s0, s1);
        float p = __expf(edge_score(s0, s1, hd0, hd1, at0, at1));
        den += p;
        acc[0] += p * s0.x; acc[1] += p * s0.y;
        acc[2] += p * s0.z; acc[3] += p * s0.w;
        acc[4] += p * s1.x; acc[5] += p * s1.y;
        acc[6] += p * s1.z; acc[7] += p * s1.w;
    }

    float inv = 1.0f / den;
    float q[8];
    #pragma unroll
    for (int k = 0; k < 8; k++) q[k] = acc[k] * inv;

    // head mean: lane l (<16) pairs with lane l+16 (same output channels)
    float o[8];
    #pragma unroll
    for (int k = 0; k < 8; k++) o[k] = __shfl_xor_sync(0xffffffffu, q[k], 16);

    if (lane < 16) {
        int c0 = lane * 8;
        float4 r0, r1;
        r0.x = 0.5f * (q[0] + o[0]) + __ldg(&gat_bias[c0 + 0]);
        r0.y = 0.5f * (q[1] + o[1]) + __ldg(&gat_bias[c0 + 1]);
        r0.z = 0.5f * (q[2] + o[2]) + __ldg(&gat_bias[c0 + 2]);
        r0.w = 0.5f * (q[3] + o[3]) + __ldg(&gat_bias[c0 + 3]);
        r1.x = 0.5f * (q[4] + o[4]) + __ldg(&gat_bias[c0 + 4]);
        r1.y = 0.5f * (q[5] + o[5]) + __ldg(&gat_bias[c0 + 5]);
        r1.z = 0.5f * (q[6] + o[6]) + __ldg(&gat_bias[c0 + 6]);
        r1.w = 0.5f * (q[7] + o[7]) + __ldg(&gat_bias[c0 + 7]);
        float4* op = (float4*)g_pre;
        op[(size_t)i * 32 + lane * 2]     = r0;
        op[(size_t)i * 32 + lane * 2 + 1] = r1;
    }
}

// ---------------- K6: BN statistics (sum, sumsq per channel) -------------
__global__ void k_bnstats() {
    __shared__ float ssum[256], ssq[256];
    int c = threadIdx.x & 127;
    int g = threadIdx.x >> 7;          // 0 or 1
    int rbase = blockIdx.x * 128;
    float sum = 0.f, sq = 0.f;
    for (int r = rbase + g; r < rbase + 128; r += 2) {
        float v = g_pre[(size_t)r * 128 + c];
        sum += v; sq += v * v;
    }
    ssum[threadIdx.x] = sum;
    ssq[threadIdx.x]  = sq;
    __syncthreads();
    if (g == 0) {
        double S = (double)ssum[c] + (double)ssum[c + 128];
        double Q = (double)ssq[c]  + (double)ssq[c + 128];
        atomicAdd(&g_sum[c], S);
        atomicAdd(&g_sq[c], Q);
    }
}

// ------- K7: BN fold + apply + LeakyReLU + transpose (32x32 tiles) -------
__global__ void k_final(const float* __restrict__ gamma,
                        const float* __restrict__ beta,
                        float* __restrict__ out) {
    __shared__ float t[32][33];
    __shared__ float ssc[32], ssh[32];
    int c0 = blockIdx.y * 32;
    int s0 = blockIdx.x * 32;
    int b  = blockIdx.z;
    int x = threadIdx.x;          // 0..31
    int y = threadIdx.y;          // 0..7

    if (y == 0) {
        int c = c0 + x;
        double mean = g_sum[c] / (double)N_NODES;
        double var  = g_sq[c] / (double)N_NODES - mean * mean;
        float inv = (float)(1.0 / sqrt(var + 1e-5));
        float a = gamma[c] * inv;
        ssc[x] = a;
        ssh[x] = beta[c] - (float)mean * a;
    }

    #pragma unroll
    for (int i = y; i < 32; i += 8)
        t[i][x] = g_pre[(size_t)(b * DHW + s0 + i) * 128 + c0 + x];
    __syncthreads();

    #pragma unroll
    for (int i = y; i < 32; i += 8) {
        float v = t[x][i] * ssc[i] + ssh[i];
        out[((size_t)b * OUTC + c0 + i) * DHW + s0 + x] = fmaxf(v, NEG_ACT * v);
    }
}

// ---------------- launch ----------------
extern "C" void kernel_launch(void* const* d_in, const int* in_sizes, int n_in,
                              void* d_out, int out_size) {
    const float* x        = (const float*)d_in[0];
    const int*   ei       = (const int*)d_in[1];     // int64 downcast to int32
    const float* lin_w    = (const float*)d_in[2];
    const float* lin_b    = (const float*)d_in[3];
    const float* att      = (const float*)d_in[4];
    const float* gat_bias = (const float*)d_in[5];
    const float* bn_gamma = (const float*)d_in[6];
    const float* bn_beta  = (const float*)d_in[7];
    float*       out      = (float*)d_out;

    k_zero<<<(N_NODES + 255) / 256, 256>>>();
    k_gemm<<<N_NODES / 16, 256>>>(x, lin_w, lin_b);
    k_deg<<<(E_EDGES + 255) / 256, 256>>>(ei);
    k_scan<<<16, 1024>>>();
    k_scatter<<<(E_EDGES + 255) / 256, 256>>>(ei);
    k_attn<<<(N_NODES * 32) / 128, 128>>>(att, gat_bias);
    k_bnstats<<<N_NODES / 128, 256>>>();
    dim3 ftb(32, 8);
    dim3 fgr(DHW / 32, OUTC / 32, BATCH);
    k_final<<<fgr, ftb>>>(bn_gamma, bn_beta, out);
}